// round 1
// baseline (speedup 1.0000x reference)
#include <cuda_runtime.h>
#include <math.h>

// Problem constants
#define D_IN    2048
#define HEADS   16
#define GROUPS  2
#define HD      128
#define BATCH   8
#define SEQ     512
#define CACHE   256
#define T_TOT   768          // CACHE + SEQ
#define M_ROWS  (BATCH*SEQ)  // 4096
#define OUT_O_SIZE (M_ROWS*D_IN)            // 8388608
#define OUT_K_SIZE (BATCH*T_TOT*GROUPS*HD)  // 1572864

// Scratch (device globals — no runtime allocation)
__device__ float g_q_raw[M_ROWS * D_IN];            // raw q (b*s, 2048)
__device__ float g_k_raw[M_ROWS * GROUPS * HD];     // raw k (b*s, 256)
__device__ float g_q[M_ROWS * D_IN];                // roped+scaled q, layout (b,h,s,hd)
__device__ float g_attn[M_ROWS * D_IN];             // attention out, layout (b,s,h*hd)

// ---------------------------------------------------------------------------
// Fused QKV GEMM: x(4096x2048) @ {Wq|Wk|Wv} + bias
// grid.x = 32 row tiles, grid.y = 20 col tiles (16 q, 2 k, 2 v)
// ---------------------------------------------------------------------------
__global__ void __launch_bounds__(256) gemm_qkv_kernel(
    const float* __restrict__ x,
    const float* __restrict__ Wq, const float* __restrict__ bq,
    const float* __restrict__ Wk, const float* __restrict__ bk,
    const float* __restrict__ Wv, const float* __restrict__ bv,
    float* __restrict__ out_v)
{
    const int K = D_IN;
    int by = blockIdx.y;
    const float* W; const float* bias; int ldB; int mode; int n0;
    if (by < 16)      { W = Wq; bias = bq; ldB = D_IN; mode = 0; n0 = by * 128; }
    else if (by < 18) { W = Wk; bias = bk; ldB = 256;  mode = 1; n0 = (by-16) * 128; }
    else              { W = Wv; bias = bv; ldB = 256;  mode = 2; n0 = (by-18) * 128; }

    __shared__ float As[8][128];
    __shared__ float Bs[8][128];

    int tid = threadIdx.x;
    int tx = tid & 15, ty = tid >> 4;
    int row0 = blockIdx.x * 128;

    int a_row = tid >> 1;
    int a_c4  = (tid & 1) * 4;
    int b_row = tid >> 5;
    int b_c4  = (tid & 31) * 4;

    float acc[8][8];
    #pragma unroll
    for (int i = 0; i < 8; i++)
        #pragma unroll
        for (int j = 0; j < 8; j++) acc[i][j] = 0.f;

    for (int k0 = 0; k0 < K; k0 += 8) {
        float4 av = *(const float4*)&x[(size_t)(row0 + a_row) * K + k0 + a_c4];
        As[a_c4+0][a_row] = av.x; As[a_c4+1][a_row] = av.y;
        As[a_c4+2][a_row] = av.z; As[a_c4+3][a_row] = av.w;
        float4 bv4 = *(const float4*)&W[(size_t)(k0 + b_row) * ldB + n0 + b_c4];
        *(float4*)&Bs[b_row][b_c4] = bv4;
        __syncthreads();
        #pragma unroll
        for (int kk = 0; kk < 8; kk++) {
            float ra[8], rb[8];
            #pragma unroll
            for (int i = 0; i < 8; i++) ra[i] = As[kk][ty*8 + i];
            #pragma unroll
            for (int j = 0; j < 8; j++) rb[j] = Bs[kk][tx*8 + j];
            #pragma unroll
            for (int i = 0; i < 8; i++)
                #pragma unroll
                for (int j = 0; j < 8; j++)
                    acc[i][j] = fmaf(ra[i], rb[j], acc[i][j]);
        }
        __syncthreads();
    }

    #pragma unroll
    for (int i = 0; i < 8; i++) {
        int m = row0 + ty*8 + i;
        #pragma unroll
        for (int j = 0; j < 8; j++) {
            int c = tx*8 + j;
            float v = acc[i][j] + bias[n0 + c];
            if (mode == 0) {
                g_q_raw[(size_t)m * D_IN + n0 + c] = v;
            } else if (mode == 1) {
                g_k_raw[(size_t)m * 256 + n0 + c] = v;
            } else {
                int b = m >> 9, s = m & 511, g = n0 >> 7;
                out_v[(((size_t)b * T_TOT + CACHE + s) * GROUPS + g) * HD + c] = v;
            }
        }
    }
}

// ---------------------------------------------------------------------------
// Output projection GEMM: g_attn(4096x2048) @ Wo + bo -> out_o
// ---------------------------------------------------------------------------
__global__ void __launch_bounds__(256) gemm_out_kernel(
    const float* __restrict__ Wo, const float* __restrict__ bo,
    float* __restrict__ out_o)
{
    const int K = D_IN, N = D_IN;
    __shared__ float As[8][128];
    __shared__ float Bs[8][128];

    int tid = threadIdx.x;
    int tx = tid & 15, ty = tid >> 4;
    int row0 = blockIdx.x * 128;
    int n0 = blockIdx.y * 128;

    int a_row = tid >> 1;
    int a_c4  = (tid & 1) * 4;
    int b_row = tid >> 5;
    int b_c4  = (tid & 31) * 4;

    float acc[8][8];
    #pragma unroll
    for (int i = 0; i < 8; i++)
        #pragma unroll
        for (int j = 0; j < 8; j++) acc[i][j] = 0.f;

    for (int k0 = 0; k0 < K; k0 += 8) {
        float4 av = *(const float4*)&g_attn[(size_t)(row0 + a_row) * K + k0 + a_c4];
        As[a_c4+0][a_row] = av.x; As[a_c4+1][a_row] = av.y;
        As[a_c4+2][a_row] = av.z; As[a_c4+3][a_row] = av.w;
        float4 bv4 = *(const float4*)&Wo[(size_t)(k0 + b_row) * N + n0 + b_c4];
        *(float4*)&Bs[b_row][b_c4] = bv4;
        __syncthreads();
        #pragma unroll
        for (int kk = 0; kk < 8; kk++) {
            float ra[8], rb[8];
            #pragma unroll
            for (int i = 0; i < 8; i++) ra[i] = As[kk][ty*8 + i];
            #pragma unroll
            for (int j = 0; j < 8; j++) rb[j] = Bs[kk][tx*8 + j];
            #pragma unroll
            for (int i = 0; i < 8; i++)
                #pragma unroll
                for (int j = 0; j < 8; j++)
                    acc[i][j] = fmaf(ra[i], rb[j], acc[i][j]);
        }
        __syncthreads();
    }

    #pragma unroll
    for (int i = 0; i < 8; i++) {
        int m = row0 + ty*8 + i;
        #pragma unroll
        for (int j = 0; j < 8; j++) {
            int c = tx*8 + j;
            out_o[(size_t)m * N + n0 + c] = acc[i][j] + bo[n0 + c];
        }
    }
}

// ---------------------------------------------------------------------------
// RoPE on q: read g_q_raw (b*s, 2048), write g_q in (b,h,s,hd) layout, *scale
// ---------------------------------------------------------------------------
__global__ void rope_q_kernel()
{
    int idx = blockIdx.x * blockDim.x + threadIdx.x;  // < 4096*16*64
    int j = idx & 63;
    int h = (idx >> 6) & 15;
    int m = idx >> 10;
    const float* src = g_q_raw + (size_t)m * D_IN + h * HD;
    float x1 = src[j], x2 = src[j + 64];
    int s = m & 511, b = m >> 9;
    float pos = (float)(CACHE + s);
    // inv_freq = 10000^(-j/64)
    float freq = pos * expf(-(float)j * (9.210340371976184f / 64.f));
    float sn, cs; sincosf(freq, &sn, &cs);
    const float SCALE = 0.08838834764831845f;  // 128^-0.5
    float* dst = g_q + (((size_t)b * HEADS + h) * SEQ + s) * HD;
    dst[j]      = (x1 * cs - x2 * sn) * SCALE;
    dst[j + 64] = (x2 * cs + x1 * sn) * SCALE;
}

// ---------------------------------------------------------------------------
// RoPE on k: read g_k_raw, write into out_k cache region rows [256,768)
// ---------------------------------------------------------------------------
__global__ void rope_k_kernel(float* __restrict__ out_k)
{
    int idx = blockIdx.x * blockDim.x + threadIdx.x;  // < 4096*2*64
    int j = idx & 63;
    int g = (idx >> 6) & 1;
    int m = idx >> 7;
    const float* src = g_k_raw + (size_t)m * 256 + g * HD;
    float x1 = src[j], x2 = src[j + 64];
    int s = m & 511, b = m >> 9;
    float pos = (float)(CACHE + s);
    float freq = pos * expf(-(float)j * (9.210340371976184f / 64.f));
    float sn, cs; sincosf(freq, &sn, &cs);
    float* dst = out_k + (((size_t)b * T_TOT + CACHE + s) * GROUPS + g) * HD;
    dst[j]      = x1 * cs - x2 * sn;
    dst[j + 64] = x2 * cs + x1 * sn;
}

// ---------------------------------------------------------------------------
// Copy prev_k / prev_v into cache rows [0,256)
// ---------------------------------------------------------------------------
__global__ void copy_prev_kernel(const float* __restrict__ prev_k,
                                 const float* __restrict__ prev_v,
                                 float* __restrict__ out_k,
                                 float* __restrict__ out_v)
{
    int idx = blockIdx.x * blockDim.x + threadIdx.x;  // < 8*256*256
    if (idx >= BATCH * CACHE * GROUPS * HD) return;
    int b = idx >> 16;          // /(256*256)
    int r = idx & 65535;
    out_k[(size_t)b * (T_TOT * GROUPS * HD) + r] = prev_k[idx];
    out_v[(size_t)b * (T_TOT * GROUPS * HD) + r] = prev_v[idx];
}

// ---------------------------------------------------------------------------
// Flash attention: Q tile 128, K tile 64, online softmax.
// grid = (SEQ/128 = 4, BATCH*HEADS = 128), 256 threads.
// Dynamic smem: Qs[128][128] + Ks[64][129] + Vs[64][132] + Ps[128][65]
// ---------------------------------------------------------------------------
#define ATTN_SMEM_FLOATS (128*128 + 64*129 + 64*132 + 128*65)

__global__ void __launch_bounds__(256) attn_kernel(
    const float* __restrict__ kbase, const float* __restrict__ vbase)
{
    extern __shared__ float sm[];
    float* Qs = sm;                       // 128 x 128
    float* Ks = Qs + 128*128;             // 64 x 129 (padded)
    float* Vs = Ks + 64*129;              // 64 x 132 (padded, float4-aligned rows)
    float* Ps = Vs + 64*132;              // 128 x 65 (padded)

    int bh = blockIdx.y;
    int b = bh >> 4, h = bh & 15;
    int g = h >> 3;
    int q0 = blockIdx.x * 128;

    int tid = threadIdx.x;
    int tx = tid & 15, ty = tid >> 4;

    // Load Q tile (scale already folded in by rope_q)
    const float* qsrc = g_q + (((size_t)b * HEADS + h) * SEQ + q0) * HD;
    #pragma unroll
    for (int it = 0; it < 16; it++) {
        int fidx = tid + it * 256;        // 0..4095 float4s
        int r = fidx >> 5, c4 = (fidx & 31) * 4;
        *(float4*)&Qs[r * 128 + c4] = *(const float4*)&qsrc[(size_t)r * 128 + c4];
    }

    float m_[8], l_[8], O[8][8];
    #pragma unroll
    for (int i = 0; i < 8; i++) {
        m_[i] = -1e30f; l_[i] = 0.f;
        #pragma unroll
        for (int j = 0; j < 8; j++) O[i][j] = 0.f;
    }

    const float* kptr = kbase + ((size_t)b * T_TOT * GROUPS + g) * HD;
    const float* vptr = vbase + ((size_t)b * T_TOT * GROUPS + g) * HD;

    __syncthreads();

    for (int kt = 0; kt < T_TOT; kt += 64) {
        // Load K,V tiles (64 x 128 each); consecutive t rows stride 256 floats
        #pragma unroll
        for (int it = 0; it < 8; it++) {
            int fidx = tid + it * 256;    // 0..2047 float4s
            int r = fidx >> 5, c4 = (fidx & 31) * 4;
            float4 kv = *(const float4*)&kptr[(size_t)(kt + r) * (GROUPS*HD) + c4];
            Ks[r*129 + c4+0] = kv.x; Ks[r*129 + c4+1] = kv.y;
            Ks[r*129 + c4+2] = kv.z; Ks[r*129 + c4+3] = kv.w;
            float4 vv = *(const float4*)&vptr[(size_t)(kt + r) * (GROUPS*HD) + c4];
            *(float4*)&Vs[r*132 + c4] = vv;
        }
        __syncthreads();

        // GEMM1: S[128,64] = Q @ K^T ; per thread 8 rows x 4 cols
        float s_[8][4];
        #pragma unroll
        for (int i = 0; i < 8; i++)
            #pragma unroll
            for (int j = 0; j < 4; j++) s_[i][j] = 0.f;

        for (int kk = 0; kk < 128; kk++) {
            float rq[8], rk[4];
            #pragma unroll
            for (int i = 0; i < 8; i++) rq[i] = Qs[(ty*8 + i) * 128 + kk];
            #pragma unroll
            for (int j = 0; j < 4; j++) rk[j] = Ks[(tx*4 + j) * 129 + kk];
            #pragma unroll
            for (int i = 0; i < 8; i++)
                #pragma unroll
                for (int j = 0; j < 4; j++)
                    s_[i][j] = fmaf(rq[i], rk[j], s_[i][j]);
        }

        // Online softmax update (row reductions across the 16 tx lanes)
        #pragma unroll
        for (int i = 0; i < 8; i++) {
            float mx = fmaxf(fmaxf(s_[i][0], s_[i][1]), fmaxf(s_[i][2], s_[i][3]));
            #pragma unroll
            for (int off = 8; off >= 1; off >>= 1)
                mx = fmaxf(mx, __shfl_xor_sync(0xffffffffu, mx, off));
            float mn = fmaxf(m_[i], mx);
            float sc = __expf(m_[i] - mn);
            float sum = 0.f;
            #pragma unroll
            for (int j = 0; j < 4; j++) {
                float p = __expf(s_[i][j] - mn);
                s_[i][j] = p;
                sum += p;
            }
            #pragma unroll
            for (int off = 8; off >= 1; off >>= 1)
                sum += __shfl_xor_sync(0xffffffffu, sum, off);
            l_[i] = l_[i] * sc + sum;
            #pragma unroll
            for (int c = 0; c < 8; c++) O[i][c] *= sc;
            m_[i] = mn;
        }

        // Store P tile
        #pragma unroll
        for (int i = 0; i < 8; i++)
            #pragma unroll
            for (int j = 0; j < 4; j++)
                Ps[(ty*8 + i) * 65 + tx*4 + j] = s_[i][j];
        __syncthreads();

        // GEMM2: O[128,128] += P[128,64] @ V[64,128]
        for (int kk = 0; kk < 64; kk++) {
            float rp[8];
            #pragma unroll
            for (int i = 0; i < 8; i++) rp[i] = Ps[(ty*8 + i) * 65 + kk];
            float4 v0 = *(const float4*)&Vs[kk*132 + tx*8];
            float4 v1 = *(const float4*)&Vs[kk*132 + tx*8 + 4];
            #pragma unroll
            for (int i = 0; i < 8; i++) {
                O[i][0] = fmaf(rp[i], v0.x, O[i][0]);
                O[i][1] = fmaf(rp[i], v0.y, O[i][1]);
                O[i][2] = fmaf(rp[i], v0.z, O[i][2]);
                O[i][3] = fmaf(rp[i], v0.w, O[i][3]);
                O[i][4] = fmaf(rp[i], v1.x, O[i][4]);
                O[i][5] = fmaf(rp[i], v1.y, O[i][5]);
                O[i][6] = fmaf(rp[i], v1.z, O[i][6]);
                O[i][7] = fmaf(rp[i], v1.w, O[i][7]);
            }
        }
        __syncthreads();
    }

    // Epilogue: normalize, write g_attn (b,s,h*hd)
    #pragma unroll
    for (int i = 0; i < 8; i++) {
        float inv = 1.f / l_[i];
        int srow = q0 + ty*8 + i;
        float* dst = g_attn + ((size_t)b * SEQ + srow) * D_IN + h * HD + tx*8;
        float4 o0 = make_float4(O[i][0]*inv, O[i][1]*inv, O[i][2]*inv, O[i][3]*inv);
        float4 o1 = make_float4(O[i][4]*inv, O[i][5]*inv, O[i][6]*inv, O[i][7]*inv);
        *(float4*)&dst[0] = o0;
        *(float4*)&dst[4] = o1;
    }
}

// ---------------------------------------------------------------------------
extern "C" void kernel_launch(void* const* d_in, const int* in_sizes, int n_in,
                              void* d_out, int out_size)
{
    const float* x      = (const float*)d_in[0];
    const float* prev_k = (const float*)d_in[1];
    const float* prev_v = (const float*)d_in[2];
    const float* Wq     = (const float*)d_in[3];
    const float* bq     = (const float*)d_in[4];
    const float* Wk     = (const float*)d_in[5];
    const float* bk     = (const float*)d_in[6];
    const float* Wv     = (const float*)d_in[7];
    const float* bv     = (const float*)d_in[8];
    const float* Wo     = (const float*)d_in[9];
    const float* bo     = (const float*)d_in[10];

    float* out_o = (float*)d_out;
    float* out_k = out_o + OUT_O_SIZE;
    float* out_v = out_k + OUT_K_SIZE;

    // Attention kernel needs large dynamic smem
    static bool attr_set = false;
    size_t attn_smem = ATTN_SMEM_FLOATS * sizeof(float);
    if (!attr_set) {
        cudaFuncSetAttribute(attn_kernel, cudaFuncAttributeMaxDynamicSharedMemorySize,
                             (int)attn_smem);
        attr_set = true;
    }

    // 1. Copy kv cache history into output regions
    {
        int n = BATCH * CACHE * GROUPS * HD;  // 524288
        copy_prev_kernel<<<(n + 255) / 256, 256>>>(prev_k, prev_v, out_k, out_v);
    }

    // 2. Fused QKV projection (v written directly into out_v cache region)
    {
        dim3 grid(M_ROWS / 128, 20);
        gemm_qkv_kernel<<<grid, 256>>>(x, Wq, bq, Wk, bk, Wv, bv, out_v);
    }

    // 3. RoPE q (with softmax scale folded) and RoPE k (into out_k)
    {
        int nq = M_ROWS * HEADS * 64;   // 4194304
        rope_q_kernel<<<nq / 256, 256>>>();
        int nk = M_ROWS * GROUPS * 64;  // 524288
        rope_k_kernel<<<nk / 256, 256>>>(out_k);
    }

    // 4. Flash attention
    {
        dim3 grid(SEQ / 128, BATCH * HEADS);
        attn_kernel<<<grid, 256, attn_smem>>>(out_k, out_v);
    }

    // 5. Output projection
    {
        dim3 grid(M_ROWS / 128, D_IN / 128);
        gemm_out_kernel<<<grid, 256>>>(Wo, bo, out_o);
    }
}

// round 3
// speedup vs baseline: 2.8908x; 2.8908x over previous
#include <cuda_runtime.h>
#include <cstdint>
#include <math.h>

// ---------------------------------------------------------------- constants
#define D_IN    2048
#define HEADS   16
#define GROUPS  2
#define HD      128
#define BATCH   8
#define SEQ     512
#define CACHE   256
#define T_TOT   768
#define M_ROWS  (BATCH*SEQ)                 // 4096
#define QKV_N   2560                        // 2048 q + 256 k + 256 v
#define OUT_O_SIZE (M_ROWS*D_IN)            // 8388608
#define OUT_K_SIZE (BATCH*T_TOT*GROUPS*HD)  // 1572864

// ---------------------------------------------------------------- scratch
__device__ float g_qkv[M_ROWS * QKV_N];
__device__ float g_q[M_ROWS * D_IN];          // roped+scaled q, per (b,g): rows r*512+s
__device__ float g_attn[M_ROWS * D_IN];       // attention out (b,s,h*hd)
__device__ float g_scores[16 * 4096 * T_TOT]; // per (b,g): (r*s, T)

// ---------------------------------------------------------------- helpers
__device__ __forceinline__ uint32_t f2tf32(float f) {
    uint32_t r;
    asm("cvt.rna.tf32.f32 %0, %1;" : "=r"(r) : "f"(f));
    return r;
}

__device__ __forceinline__ void mma_tf32(float c[4],
                                         uint32_t a0, uint32_t a1, uint32_t a2, uint32_t a3,
                                         uint32_t b0, uint32_t b1) {
    asm volatile(
        "mma.sync.aligned.m16n8k8.row.col.f32.tf32.tf32.f32 "
        "{%0,%1,%2,%3}, {%4,%5,%6,%7}, {%8,%9}, {%0,%1,%2,%3};"
        : "+f"(c[0]), "+f"(c[1]), "+f"(c[2]), "+f"(c[3])
        : "r"(a0), "r"(a1), "r"(a2), "r"(a3), "r"(b0), "r"(b1));
}

// ---------------------------------------------------------------- GEMM core
// Block tile 128x128, K chunk 32. 256 threads = 8 warps in 4(m) x 2(n).
// Each warp: 32(m) x 64(n) = 2 mtiles x 8 ntiles of m16n8k8.
// smem: 2 stages x (A[128][36] + B[128][36]) floats (tf32 bits).
#define SROW 36
#define STAGE_FLOATS (2 * 128 * SROW)     // A+B one stage = 9216
#define GEMM_SMEM_BYTES (2 * STAGE_FLOATS * 4)  // 73728

template<bool TRANSB>
__device__ __forceinline__ void mma_gemm(
    const float* __restrict__ A, int lda,
    const float* __restrict__ B, int ldb,
    int n_chunks, float* sm, float c[2][8][4])
{
    const int tid  = threadIdx.x;
    const int lane = tid & 31;
    const int wid  = tid >> 5;
    const int wm   = wid >> 1;     // 0..3
    const int wn   = wid & 1;      // 0..1

    // staging coordinates
    const int arow = tid >> 1;            // 0..127
    const int acol = (tid & 1) * 16;      // 0 or 16
    const int bn   = tid & 127;           // trans path: n index
    const int bkb  = (tid >> 7) * 16;     // trans path: k sub-offset

    float regA[16], regB[16];

    auto ldg_chunk = [&](int i) {
        const float* ap = A + (size_t)arow * lda + i * 32 + acol;
        #pragma unroll
        for (int q = 0; q < 4; q++) {
            float4 v = *(const float4*)(ap + q * 4);
            regA[q*4+0] = v.x; regA[q*4+1] = v.y; regA[q*4+2] = v.z; regA[q*4+3] = v.w;
        }
        if (!TRANSB) {
            const float* bp = B + (size_t)arow * ldb + i * 32 + acol;
            #pragma unroll
            for (int q = 0; q < 4; q++) {
                float4 v = *(const float4*)(bp + q * 4);
                regB[q*4+0] = v.x; regB[q*4+1] = v.y; regB[q*4+2] = v.z; regB[q*4+3] = v.w;
            }
        } else {
            const float* bp = B + (size_t)(i * 32 + bkb) * ldb + bn;
            #pragma unroll
            for (int j = 0; j < 16; j++)
                regB[j] = bp[(size_t)j * ldb];
        }
    };

    auto sts_chunk = [&](int s) {
        uint32_t* As = (uint32_t*)(sm + s * STAGE_FLOATS);
        uint32_t* Bs = As + 128 * SROW;
        #pragma unroll
        for (int q = 0; q < 4; q++) {
            uint4 u = make_uint4(f2tf32(regA[q*4+0]), f2tf32(regA[q*4+1]),
                                 f2tf32(regA[q*4+2]), f2tf32(regA[q*4+3]));
            *(uint4*)&As[arow * SROW + acol + q * 4] = u;
        }
        if (!TRANSB) {
            #pragma unroll
            for (int q = 0; q < 4; q++) {
                uint4 u = make_uint4(f2tf32(regB[q*4+0]), f2tf32(regB[q*4+1]),
                                     f2tf32(regB[q*4+2]), f2tf32(regB[q*4+3]));
                *(uint4*)&Bs[arow * SROW + acol + q * 4] = u;
            }
        } else {
            #pragma unroll
            for (int j = 0; j < 16; j++)
                Bs[bn * SROW + bkb + j] = f2tf32(regB[j]);
        }
    };

    auto compute = [&](int s) {
        const uint32_t* As = (const uint32_t*)(sm + s * STAGE_FLOATS);
        const uint32_t* Bs = As + 128 * SROW;
        const uint32_t* ap = As + (wm * 32 + (lane >> 2)) * SROW + (lane & 3);
        const uint32_t* bp = Bs + (wn * 64 + (lane >> 2)) * SROW + (lane & 3);
        #pragma unroll
        for (int ks = 0; ks < 4; ks++) {
            uint32_t af[2][4];
            #pragma unroll
            for (int mt = 0; mt < 2; mt++) {
                const uint32_t* p = ap + mt * 16 * SROW + ks * 8;
                af[mt][0] = p[0];
                af[mt][1] = p[8 * SROW];
                af[mt][2] = p[4];
                af[mt][3] = p[8 * SROW + 4];
            }
            #pragma unroll
            for (int nt = 0; nt < 8; nt++) {
                const uint32_t* p = bp + nt * 8 * SROW + ks * 8;
                uint32_t b0 = p[0], b1 = p[4];
                #pragma unroll
                for (int mt = 0; mt < 2; mt++)
                    mma_tf32(c[mt][nt], af[mt][0], af[mt][1], af[mt][2], af[mt][3], b0, b1);
            }
        }
    };

    #pragma unroll
    for (int mt = 0; mt < 2; mt++)
        #pragma unroll
        for (int nt = 0; nt < 8; nt++)
            #pragma unroll
            for (int q = 0; q < 4; q++) c[mt][nt][q] = 0.f;

    ldg_chunk(0);
    sts_chunk(0);
    __syncthreads();
    for (int i = 0; i < n_chunks; i++) {
        if (i + 1 < n_chunks) ldg_chunk(i + 1);
        compute(i & 1);
        if (i + 1 < n_chunks) sts_chunk((i + 1) & 1);
        __syncthreads();
    }
}

// Epilogue coordinate helpers (within 128x128 tile)
#define EPI_ROW(mt, half)  (( (threadIdx.x >> 6) & 3 ) * 32 + (mt) * 16 + ((threadIdx.x & 31) >> 2) + (half) * 8)
#define EPI_COL(nt)        (( (threadIdx.x >> 5) & 1 ) * 64 + (nt) * 8 + ((threadIdx.x & 31) & 3) * 2)

// ---------------------------------------------------------------- kernels

// QKV projection: x(4096x2048) @ {Wq|Wk|Wv} + bias -> g_qkv(4096x2560)
__global__ void __launch_bounds__(256) qkv_gemm_kernel(
    const float* __restrict__ x,
    const float* __restrict__ Wq, const float* __restrict__ bq,
    const float* __restrict__ Wk, const float* __restrict__ bk,
    const float* __restrict__ Wv, const float* __restrict__ bv)
{
    extern __shared__ float sm[];
    int by = blockIdx.y;
    const float* W; const float* bias; int ldw, wn0;
    if (by < 16)      { W = Wq; bias = bq; ldw = 2048; wn0 = by * 128; }
    else if (by < 18) { W = Wk; bias = bk; ldw = 256;  wn0 = (by - 16) * 128; }
    else              { W = Wv; bias = bv; ldw = 256;  wn0 = (by - 18) * 128; }
    int row0 = blockIdx.x * 128;
    int gcol = by * 128;

    float c[2][8][4];
    mma_gemm<true>(x + (size_t)row0 * D_IN, D_IN, W + wn0, ldw, D_IN / 32, sm, c);

    #pragma unroll
    for (int mt = 0; mt < 2; mt++)
        #pragma unroll
        for (int half = 0; half < 2; half++) {
            int r = row0 + EPI_ROW(mt, half);
            #pragma unroll
            for (int nt = 0; nt < 8; nt++) {
                int cl = EPI_COL(nt);
                float2 v;
                v.x = c[mt][nt][half*2+0] + bias[wn0 + cl];
                v.y = c[mt][nt][half*2+1] + bias[wn0 + cl + 1];
                *(float2*)&g_qkv[(size_t)r * QKV_N + gcol + cl] = v;
            }
        }
}

// Scores: per (b,g): g_q(4096x128) @ k_cache^T -> g_scores(4096x768)
__global__ void __launch_bounds__(256) scores_gemm_kernel(const float* __restrict__ kcache)
{
    extern __shared__ float sm[];
    int bg = blockIdx.z;
    int b = bg >> 1, g = bg & 1;
    int row0 = blockIdx.x * 128;
    int n0 = blockIdx.y * 128;

    const float* A = g_q + (size_t)bg * 4096 * HD + (size_t)row0 * HD;
    const float* B = kcache + ((size_t)b * T_TOT + n0) * (GROUPS * HD) + g * HD;

    float c[2][8][4];
    mma_gemm<false>(A, HD, B, GROUPS * HD, HD / 32, sm, c);

    float* base = g_scores + (size_t)bg * 4096 * T_TOT;
    #pragma unroll
    for (int mt = 0; mt < 2; mt++)
        #pragma unroll
        for (int half = 0; half < 2; half++) {
            int r = row0 + EPI_ROW(mt, half);
            #pragma unroll
            for (int nt = 0; nt < 8; nt++) {
                int cl = EPI_COL(nt);
                float2 v = make_float2(c[mt][nt][half*2+0], c[mt][nt][half*2+1]);
                *(float2*)&base[(size_t)r * T_TOT + n0 + cl] = v;
            }
        }
}

// PV: per (b,g): probs(4096x768) @ v_cache(768x128) -> g_attn
__global__ void __launch_bounds__(256) pv_gemm_kernel(const float* __restrict__ vcache)
{
    extern __shared__ float sm[];
    int bg = blockIdx.y;
    int b = bg >> 1, g = bg & 1;
    int row0 = blockIdx.x * 128;

    const float* A = g_scores + (size_t)bg * 4096 * T_TOT + (size_t)row0 * T_TOT;
    const float* B = vcache + (size_t)b * T_TOT * (GROUPS * HD) + g * HD;

    float c[2][8][4];
    mma_gemm<true>(A, T_TOT, B, GROUPS * HD, T_TOT / 32, sm, c);

    #pragma unroll
    for (int mt = 0; mt < 2; mt++)
        #pragma unroll
        for (int half = 0; half < 2; half++) {
            int m = row0 + EPI_ROW(mt, half);
            int rh = m >> 9, s_ = m & 511;
            float* dst = g_attn + ((size_t)b * SEQ + s_) * D_IN + (g * 8 + rh) * HD;
            #pragma unroll
            for (int nt = 0; nt < 8; nt++) {
                int cl = EPI_COL(nt);
                float2 v = make_float2(c[mt][nt][half*2+0], c[mt][nt][half*2+1]);
                *(float2*)&dst[cl] = v;
            }
        }
}

// Output projection: g_attn(4096x2048) @ Wo + bo -> out_o
__global__ void __launch_bounds__(256) outproj_gemm_kernel(
    const float* __restrict__ Wo, const float* __restrict__ bo,
    float* __restrict__ out_o)
{
    extern __shared__ float sm[];
    int row0 = blockIdx.x * 128;
    int n0 = blockIdx.y * 128;

    float c[2][8][4];
    mma_gemm<true>(g_attn + (size_t)row0 * D_IN, D_IN, Wo + n0, D_IN, D_IN / 32, sm, c);

    #pragma unroll
    for (int mt = 0; mt < 2; mt++)
        #pragma unroll
        for (int half = 0; half < 2; half++) {
            int r = row0 + EPI_ROW(mt, half);
            #pragma unroll
            for (int nt = 0; nt < 8; nt++) {
                int cl = EPI_COL(nt);
                float2 v;
                v.x = c[mt][nt][half*2+0] + bo[n0 + cl];
                v.y = c[mt][nt][half*2+1] + bo[n0 + cl + 1];
                *(float2*)&out_o[(size_t)r * D_IN + n0 + cl] = v;
            }
        }
}

// Softmax over rows of g_scores (65536 rows x 768), warp per row
__global__ void __launch_bounds__(256) softmax_kernel()
{
    int row = blockIdx.x * 8 + (threadIdx.x >> 5);
    int lane = threadIdx.x & 31;
    float* p = g_scores + (size_t)row * T_TOT;

    float v[24];
    #pragma unroll
    for (int j = 0; j < 6; j++) {
        float4 t = *(const float4*)(p + lane * 4 + j * 128);
        v[j*4+0] = t.x; v[j*4+1] = t.y; v[j*4+2] = t.z; v[j*4+3] = t.w;
    }
    float mx = -1e30f;
    #pragma unroll
    for (int j = 0; j < 24; j++) mx = fmaxf(mx, v[j]);
    #pragma unroll
    for (int off = 16; off >= 1; off >>= 1)
        mx = fmaxf(mx, __shfl_xor_sync(0xffffffffu, mx, off));
    float sum = 0.f;
    #pragma unroll
    for (int j = 0; j < 24; j++) { v[j] = __expf(v[j] - mx); sum += v[j]; }
    #pragma unroll
    for (int off = 16; off >= 1; off >>= 1)
        sum += __shfl_xor_sync(0xffffffffu, sum, off);
    float inv = 1.f / sum;
    #pragma unroll
    for (int j = 0; j < 6; j++) {
        float4 t = make_float4(v[j*4]*inv, v[j*4+1]*inv, v[j*4+2]*inv, v[j*4+3]*inv);
        *(float4*)(p + lane * 4 + j * 128) = t;
    }
}

// RoPE q: g_qkv q-section -> g_q (b,h,s,hd) with 1/sqrt(hd) folded
__global__ void rope_q_kernel()
{
    int idx = blockIdx.x * blockDim.x + threadIdx.x;
    int j = idx & 63;
    int h = (idx >> 6) & 15;
    int m = idx >> 10;
    const float* src = g_qkv + (size_t)m * QKV_N + h * HD;
    float x1 = src[j], x2 = src[j + 64];
    int s = m & 511, b = m >> 9;
    float pos = (float)(CACHE + s);
    float freq = pos * expf(-(float)j * (9.210340371976184f / 64.f));
    float sn, cs; sincosf(freq, &sn, &cs);
    const float SCALE = 0.08838834764831845f;
    float* dst = g_q + (((size_t)b * HEADS + h) * SEQ + s) * HD;
    dst[j]      = (x1 * cs - x2 * sn) * SCALE;
    dst[j + 64] = (x2 * cs + x1 * sn) * SCALE;
}

// RoPE k + copy v: g_qkv k/v sections -> out_k/out_v rows [256,768)
__global__ void rope_kv_kernel(float* __restrict__ out_k, float* __restrict__ out_v)
{
    int idx = blockIdx.x * blockDim.x + threadIdx.x;
    int j = idx & 63;
    int g = (idx >> 6) & 1;
    int m = idx >> 7;
    const float* ksrc = g_qkv + (size_t)m * QKV_N + 2048 + g * HD;
    const float* vsrc = g_qkv + (size_t)m * QKV_N + 2304 + g * HD;
    float x1 = ksrc[j], x2 = ksrc[j + 64];
    int s = m & 511, b = m >> 9;
    float pos = (float)(CACHE + s);
    float freq = pos * expf(-(float)j * (9.210340371976184f / 64.f));
    float sn, cs; sincosf(freq, &sn, &cs);
    size_t base = (((size_t)b * T_TOT + CACHE + s) * GROUPS + g) * HD;
    out_k[base + j]      = x1 * cs - x2 * sn;
    out_k[base + j + 64] = x2 * cs + x1 * sn;
    out_v[base + j]      = vsrc[j];
    out_v[base + j + 64] = vsrc[j + 64];
}

// Copy prev_k/prev_v into cache rows [0,256)
__global__ void copy_prev_kernel(const float* __restrict__ prev_k,
                                 const float* __restrict__ prev_v,
                                 float* __restrict__ out_k,
                                 float* __restrict__ out_v)
{
    int idx = blockIdx.x * blockDim.x + threadIdx.x;
    if (idx >= BATCH * CACHE * GROUPS * HD) return;
    int b = idx >> 16;
    int r = idx & 65535;
    out_k[(size_t)b * (T_TOT * GROUPS * HD) + r] = prev_k[idx];
    out_v[(size_t)b * (T_TOT * GROUPS * HD) + r] = prev_v[idx];
}

// ---------------------------------------------------------------- launcher
extern "C" void kernel_launch(void* const* d_in, const int* in_sizes, int n_in,
                              void* d_out, int out_size)
{
    const float* x      = (const float*)d_in[0];
    const float* prev_k = (const float*)d_in[1];
    const float* prev_v = (const float*)d_in[2];
    const float* Wq     = (const float*)d_in[3];
    const float* bq     = (const float*)d_in[4];
    const float* Wk     = (const float*)d_in[5];
    const float* bk     = (const float*)d_in[6];
    const float* Wv     = (const float*)d_in[7];
    const float* bv     = (const float*)d_in[8];
    const float* Wo     = (const float*)d_in[9];
    const float* bo     = (const float*)d_in[10];

    float* out_o = (float*)d_out;
    float* out_k = out_o + OUT_O_SIZE;
    float* out_v = out_k + OUT_K_SIZE;

    static bool attr_set = false;
    if (!attr_set) {
        cudaFuncSetAttribute(qkv_gemm_kernel,     cudaFuncAttributeMaxDynamicSharedMemorySize, GEMM_SMEM_BYTES);
        cudaFuncSetAttribute(scores_gemm_kernel,  cudaFuncAttributeMaxDynamicSharedMemorySize, GEMM_SMEM_BYTES);
        cudaFuncSetAttribute(pv_gemm_kernel,      cudaFuncAttributeMaxDynamicSharedMemorySize, GEMM_SMEM_BYTES);
        cudaFuncSetAttribute(outproj_gemm_kernel, cudaFuncAttributeMaxDynamicSharedMemorySize, GEMM_SMEM_BYTES);
        attr_set = true;
    }

    // 1. kv-cache history
    copy_prev_kernel<<<2048, 256>>>(prev_k, prev_v, out_k, out_v);

    // 2. QKV projection (tf32 mma.sync)
    qkv_gemm_kernel<<<dim3(M_ROWS/128, 20), 256, GEMM_SMEM_BYTES>>>(
        x, Wq, bq, Wk, bk, Wv, bv);

    // 3. RoPE q / RoPE k + v copy
    rope_q_kernel<<<M_ROWS * HEADS * 64 / 256, 256>>>();
    rope_kv_kernel<<<M_ROWS * GROUPS * 64 / 256, 256>>>(out_k, out_v);

    // 4. Scores GEMM
    scores_gemm_kernel<<<dim3(32, T_TOT/128, 16), 256, GEMM_SMEM_BYTES>>>(out_k);

    // 5. Softmax
    softmax_kernel<<<(16 * 4096) / 8, 256>>>();

    // 6. PV GEMM
    pv_gemm_kernel<<<dim3(32, 16), 256, GEMM_SMEM_BYTES>>>(out_v);

    // 7. Output projection
    outproj_gemm_kernel<<<dim3(M_ROWS/128, D_IN/128), 256, GEMM_SMEM_BYTES>>>(
        Wo, bo, out_o);
}